// round 6
// baseline (speedup 1.0000x reference)
#include <cuda_runtime.h>
#include <math.h>

#define N_B   2
#define C_    256
#define L_    4096
#define G_    8
#define CPG   32
#define HEADS 4
#define HD    64
#define EPSV  1e-5f
#define NCL   (N_B * C_ * L_)   // 2097152

// ---------------- scratch (static device globals; no allocation) ------------
__device__ float g_xn[NCL];
__device__ float g_q [NCL];
__device__ float g_k [NCL];
__device__ float g_v [NCL];
__device__ float g_ao[NCL];
__device__ float g_stats[N_B * G_ * 2];   // mean, rstd per (n,g)

// ---------------- GroupNorm: stats ------------------------------------------
__global__ void gn_stats_kernel(const float* __restrict__ x) {
    int ng = blockIdx.x;  // 0..15 : n*8+g, groups are contiguous channel blocks
    const float4* base = (const float4*)(x + (size_t)ng * CPG * L_);
    float s1 = 0.f, s2 = 0.f;
    const int nv = CPG * L_ / 4;  // 32768
    for (int i = threadIdx.x; i < nv; i += 256) {
        float4 v = base[i];
        s1 += (v.x + v.y) + (v.z + v.w);
        s2 += (v.x * v.x + v.y * v.y) + (v.z * v.z + v.w * v.w);
    }
    __shared__ float r1[256], r2[256];
    r1[threadIdx.x] = s1; r2[threadIdx.x] = s2;
    __syncthreads();
    for (int s = 128; s > 0; s >>= 1) {
        if (threadIdx.x < s) {
            r1[threadIdx.x] += r1[threadIdx.x + s];
            r2[threadIdx.x] += r2[threadIdx.x + s];
        }
        __syncthreads();
    }
    if (threadIdx.x == 0) {
        float cnt  = (float)(CPG * L_);
        float mean = r1[0] / cnt;
        float var  = r2[0] / cnt - mean * mean;
        g_stats[ng * 2 + 0] = mean;
        g_stats[ng * 2 + 1] = rsqrtf(var + EPSV);
    }
}

// ---------------- GroupNorm: apply ------------------------------------------
__global__ void gn_apply_kernel(const float* __restrict__ x,
                                const float* __restrict__ w,
                                const float* __restrict__ b) {
    int i = blockIdx.x * blockDim.x + threadIdx.x;
    if (i >= NCL / 4) return;
    int e  = i * 4;
    int c  = (e / L_) & (C_ - 1);
    int ng = e / (CPG * L_);
    float mean = g_stats[ng * 2 + 0], rstd = g_stats[ng * 2 + 1];
    float sw = w[c] * rstd;
    float sb = b[c] - mean * sw;
    float4 xv = ((const float4*)x)[i];
    float4 o;
    o.x = xv.x * sw + sb; o.y = xv.y * sw + sb;
    o.z = xv.z * sw + sb; o.w = xv.w * sw + sb;
    ((float4*)g_xn)[i] = o;
}

// ---------------- QKV conv1x1 GEMM: out[d,l] = sum_c w[d,c]*xn[c,l] + b[d] --
// tile 64x64, K-step 16, 256 threads, 4x4 micro-tile per thread
__global__ void __launch_bounds__(256) gemm_qkv_kernel(
    const float* __restrict__ qw, const float* __restrict__ qb,
    const float* __restrict__ kw, const float* __restrict__ kb,
    const float* __restrict__ vw, const float* __restrict__ vb) {

    int z = blockIdx.z;            // 0..5
    int batch = z / 3, which = z - batch * 3;
    const float* w; const float* bia; float* outp;
    if      (which == 0) { w = qw; bia = qb; outp = g_q; }
    else if (which == 1) { w = kw; bia = kb; outp = g_k; }
    else                 { w = vw; bia = vb; outp = g_v; }

    const float* B   = g_xn + (size_t)batch * C_ * L_;
    float*       Out = outp + (size_t)batch * C_ * L_;
    int m0 = blockIdx.y * 64, n0 = blockIdx.x * 64;

    __shared__ __align__(16) float As[16][68];
    __shared__ __align__(16) float Bs[16][64];

    int tx = threadIdx.x & 15, ty = threadIdx.x >> 4;
    float acc[4][4];
#pragma unroll
    for (int a = 0; a < 4; a++)
#pragma unroll
        for (int c = 0; c < 4; c++) acc[a][c] = 0.f;

    for (int k0 = 0; k0 < C_; k0 += 16) {
#pragma unroll
        for (int it = 0; it < 4; ++it) {
            int idx = threadIdx.x + it * 256;
            int kk = idx & 15, mm = idx >> 4;
            As[kk][mm] = w[(m0 + mm) * C_ + k0 + kk];
        }
#pragma unroll
        for (int it = 0; it < 4; ++it) {
            int idx = threadIdx.x + it * 256;
            int nn = idx & 63, kk = idx >> 6;
            Bs[kk][nn] = B[(size_t)(k0 + kk) * L_ + n0 + nn];
        }
        __syncthreads();
#pragma unroll
        for (int kk = 0; kk < 16; kk++) {
            float4 aa = *(const float4*)&As[kk][ty * 4];
            float4 bb = *(const float4*)&Bs[kk][tx * 4];
            acc[0][0] += aa.x * bb.x; acc[0][1] += aa.x * bb.y; acc[0][2] += aa.x * bb.z; acc[0][3] += aa.x * bb.w;
            acc[1][0] += aa.y * bb.x; acc[1][1] += aa.y * bb.y; acc[1][2] += aa.y * bb.z; acc[1][3] += aa.y * bb.w;
            acc[2][0] += aa.z * bb.x; acc[2][1] += aa.z * bb.y; acc[2][2] += aa.z * bb.z; acc[2][3] += aa.z * bb.w;
            acc[3][0] += aa.w * bb.x; acc[3][1] += aa.w * bb.y; acc[3][2] += aa.w * bb.z; acc[3][3] += aa.w * bb.w;
        }
        __syncthreads();
    }
#pragma unroll
    for (int im = 0; im < 4; im++) {
        int m = m0 + ty * 4 + im;
        float bv = bia[m];
        float4 o;
        o.x = acc[im][0] + bv; o.y = acc[im][1] + bv;
        o.z = acc[im][2] + bv; o.w = acc[im][3] + bv;
        *(float4*)&Out[(size_t)m * L_ + n0 + tx * 4] = o;
    }
}

// ---------------- Flash attention: Bq=64, Bk=32, online softmax -------------
__global__ void __launch_bounds__(256) attn_kernel() {
    int l0 = blockIdx.x * 64;
    int h  = blockIdx.y;
    int n  = blockIdx.z;
    int chbase = n * C_ + h * HD;
    const float* qp = g_q + (size_t)chbase * L_;
    const float* kp = g_k + (size_t)chbase * L_;
    const float* vp = g_v + (size_t)chbase * L_;

    __shared__ __align__(16) float Qs[64 * 68];
    __shared__ __align__(16) float Ks[64 * 34];
    __shared__ __align__(16) float Vs[32 * 68];
    __shared__ __align__(16) float Ps[32 * 68];

    int t  = threadIdx.x;
    int tx = t & 15, ty = t >> 4;

    // load Q tile [c][i], c=0..63, i=0..63
#pragma unroll
    for (int it = 0; it < 16; ++it) {
        int idx = t + it * 256;
        int c = idx >> 6, i = idx & 63;
        Qs[c * 68 + i] = qp[(size_t)c * L_ + l0 + i];
    }

    float O[4][4];     // [cc][r] : c = tx*4+cc, i = ty*4+r
    float m_run[4], l_run[4];
#pragma unroll
    for (int r = 0; r < 4; r++) {
        m_run[r] = -INFINITY; l_run[r] = 0.f;
#pragma unroll
        for (int cc = 0; cc < 4; cc++) O[cc][r] = 0.f;
    }
    __syncthreads();

    const float scale = 0.125f;   // hd^-0.5, hd=64

    for (int kt = 0; kt < 128; ++kt) {
        int k0 = kt * 32;
        // load K [c][j] and V transposed [j][c]
#pragma unroll
        for (int it = 0; it < 8; ++it) {
            int idx = t + it * 256;
            int c = idx >> 5, j = idx & 31;
            float kvk = kp[(size_t)c * L_ + k0 + j];
            float kvv = vp[(size_t)c * L_ + k0 + j];
            Ks[c * 34 + j] = kvk;
            Vs[j * 68 + c] = kvv;
        }
        __syncthreads();

        // S[i][j] = sum_c Q[c][i]*K[c][j] ; thread: 4 rows x 2 cols
        float s00 = 0.f, s01 = 0.f, s10 = 0.f, s11 = 0.f;
        float s20 = 0.f, s21 = 0.f, s30 = 0.f, s31 = 0.f;
#pragma unroll 16
        for (int c = 0; c < 64; c++) {
            float4 qa = *(const float4*)&Qs[c * 68 + ty * 4];
            float2 kb = *(const float2*)&Ks[c * 34 + tx * 2];
            s00 += qa.x * kb.x; s01 += qa.x * kb.y;
            s10 += qa.y * kb.x; s11 += qa.y * kb.y;
            s20 += qa.z * kb.x; s21 += qa.z * kb.y;
            s30 += qa.w * kb.x; s31 += qa.w * kb.y;
        }
        float sv[4][2] = {{s00, s01}, {s10, s11}, {s20, s21}, {s30, s31}};

        // online softmax per query row (16 lanes with same ty hold one row)
#pragma unroll
        for (int r = 0; r < 4; r++) {
            float v0 = sv[r][0] * scale, v1 = sv[r][1] * scale;
            float mloc = fmaxf(v0, v1);
#pragma unroll
            for (int off = 8; off > 0; off >>= 1)
                mloc = fmaxf(mloc, __shfl_xor_sync(0xffffffffu, mloc, off));
            float mnew  = fmaxf(m_run[r], mloc);
            float alpha = __expf(m_run[r] - mnew);
            float p0 = __expf(v0 - mnew);
            float p1 = __expf(v1 - mnew);
            float sl = p0 + p1;
#pragma unroll
            for (int off = 8; off > 0; off >>= 1)
                sl += __shfl_xor_sync(0xffffffffu, sl, off);
            l_run[r] = l_run[r] * alpha + sl;
            m_run[r] = mnew;
#pragma unroll
            for (int cc = 0; cc < 4; cc++) O[cc][r] *= alpha;
            Ps[(tx * 2 + 0) * 68 + ty * 4 + r] = p0;
            Ps[(tx * 2 + 1) * 68 + ty * 4 + r] = p1;
        }
        __syncthreads();

        // O[c][i] += sum_j V[c][j]*P[i][j]
#pragma unroll 8
        for (int j = 0; j < 32; j++) {
            float4 va = *(const float4*)&Vs[j * 68 + tx * 4];
            float4 pa = *(const float4*)&Ps[j * 68 + ty * 4];
            O[0][0] += va.x * pa.x; O[0][1] += va.x * pa.y; O[0][2] += va.x * pa.z; O[0][3] += va.x * pa.w;
            O[1][0] += va.y * pa.x; O[1][1] += va.y * pa.y; O[1][2] += va.y * pa.z; O[1][3] += va.y * pa.w;
            O[2][0] += va.z * pa.x; O[2][1] += va.z * pa.y; O[2][2] += va.z * pa.z; O[2][3] += va.z * pa.w;
            O[3][0] += va.w * pa.x; O[3][1] += va.w * pa.y; O[3][2] += va.w * pa.z; O[3][3] += va.w * pa.w;
        }
        __syncthreads();
    }

    // normalize and store
    float* ao = g_ao + (size_t)chbase * L_;
#pragma unroll
    for (int r = 0; r < 4; r++) {
        float inv = 1.f / l_run[r];
#pragma unroll
        for (int cc = 0; cc < 4; cc++)
            ao[(size_t)(tx * 4 + cc) * L_ + l0 + ty * 4 + r] = O[cc][r] * inv;
    }
}

// ---------------- projection + bias + residual ------------------------------
__global__ void __launch_bounds__(256) gemm_proj_kernel(
    const float* __restrict__ x,
    const float* __restrict__ pw, const float* __restrict__ pb,
    float* __restrict__ out) {

    int batch = blockIdx.z;
    const float* B  = g_ao + (size_t)batch * C_ * L_;
    const float* xb = x    + (size_t)batch * C_ * L_;
    float*       Ob = out  + (size_t)batch * C_ * L_;
    int m0 = blockIdx.y * 64, n0 = blockIdx.x * 64;

    __shared__ __align__(16) float As[16][68];
    __shared__ __align__(16) float Bs[16][64];

    int tx = threadIdx.x & 15, ty = threadIdx.x >> 4;
    float acc[4][4];
#pragma unroll
    for (int a = 0; a < 4; a++)
#pragma unroll
        for (int c = 0; c < 4; c++) acc[a][c] = 0.f;

    for (int k0 = 0; k0 < C_; k0 += 16) {
#pragma unroll
        for (int it = 0; it < 4; ++it) {
            int idx = threadIdx.x + it * 256;
            int kk = idx & 15, mm = idx >> 4;
            As[kk][mm] = pw[(m0 + mm) * C_ + k0 + kk];
        }
#pragma unroll
        for (int it = 0; it < 4; ++it) {
            int idx = threadIdx.x + it * 256;
            int nn = idx & 63, kk = idx >> 6;
            Bs[kk][nn] = B[(size_t)(k0 + kk) * L_ + n0 + nn];
        }
        __syncthreads();
#pragma unroll
        for (int kk = 0; kk < 16; kk++) {
            float4 aa = *(const float4*)&As[kk][ty * 4];
            float4 bb = *(const float4*)&Bs[kk][tx * 4];
            acc[0][0] += aa.x * bb.x; acc[0][1] += aa.x * bb.y; acc[0][2] += aa.x * bb.z; acc[0][3] += aa.x * bb.w;
            acc[1][0] += aa.y * bb.x; acc[1][1] += aa.y * bb.y; acc[1][2] += aa.y * bb.z; acc[1][3] += aa.y * bb.w;
            acc[2][0] += aa.z * bb.x; acc[2][1] += aa.z * bb.y; acc[2][2] += aa.z * bb.z; acc[2][3] += aa.z * bb.w;
            acc[3][0] += aa.w * bb.x; acc[3][1] += aa.w * bb.y; acc[3][2] += aa.w * bb.z; acc[3][3] += aa.w * bb.w;
        }
        __syncthreads();
    }
#pragma unroll
    for (int im = 0; im < 4; im++) {
        int m = m0 + ty * 4 + im;
        float bv = pb[m];
        size_t off = (size_t)m * L_ + n0 + tx * 4;
        float4 xv = *(const float4*)&xb[off];
        float4 o;
        o.x = acc[im][0] + bv + xv.x; o.y = acc[im][1] + bv + xv.y;
        o.z = acc[im][2] + bv + xv.z; o.w = acc[im][3] + bv + xv.w;
        *(float4*)&Ob[off] = o;
    }
}

// ---------------- mask pass-through (int32 -> float) ------------------------
__global__ void mask_copy_kernel(const int* __restrict__ mask,
                                 float* __restrict__ out, int nmask) {
    int i = blockIdx.x * blockDim.x + threadIdx.x;
    if (i < nmask) out[NCL + i] = (float)mask[i];
}

// ---------------- launch -----------------------------------------------------
extern "C" void kernel_launch(void* const* d_in, const int* in_sizes, int n_in,
                              void* d_out, int out_size) {
    const float* x    = (const float*)d_in[0];
    const int*   mask = (const int*)  d_in[1];
    const float* nw   = (const float*)d_in[2];
    const float* nb   = (const float*)d_in[3];
    const float* qw   = (const float*)d_in[4];
    const float* qb   = (const float*)d_in[5];
    const float* kw   = (const float*)d_in[6];
    const float* kb   = (const float*)d_in[7];
    const float* vw   = (const float*)d_in[8];
    const float* vb   = (const float*)d_in[9];
    const float* pw   = (const float*)d_in[10];
    const float* pb   = (const float*)d_in[11];
    float* out = (float*)d_out;

    gn_stats_kernel<<<N_B * G_, 256>>>(x);
    gn_apply_kernel<<<(NCL / 4 + 255) / 256, 256>>>(x, nw, nb);

    dim3 gq(L_ / 64, C_ / 64, N_B * 3);
    gemm_qkv_kernel<<<gq, 256>>>(qw, qb, kw, kb, vw, vb);

    dim3 ga(L_ / 64, HEADS, N_B);
    attn_kernel<<<ga, 256>>>();

    dim3 gp(L_ / 64, C_ / 64, N_B);
    gemm_proj_kernel<<<gp, 256>>>(x, pw, pb, out);

    if (out_size > NCL) {
        int extra = out_size - NCL;
        int nm = in_sizes[1] < extra ? in_sizes[1] : extra;
        mask_copy_kernel<<<(nm + 255) / 256, 256>>>(mask, out, nm);
    }
}

// round 8
// speedup vs baseline: 1.0005x; 1.0005x over previous
#include <cuda_runtime.h>
#include <math.h>

#define N_B   2
#define C_    256
#define L_    4096
#define G_    8
#define CPG   32
#define HEADS 4
#define HD    64
#define EPSV  1e-5f
#define NCL   (N_B * C_ * L_)   // 2097152

// ---------------- scratch (static device globals; no allocation) ------------
__device__ float g_xn[NCL];
__device__ float g_q [NCL];
__device__ float g_k [NCL];
__device__ float g_v [NCL];
__device__ float g_ao[NCL];
__device__ float g_stats[N_B * G_ * 2];   // mean, rstd per (n,g)

// ---------------- GroupNorm: stats ------------------------------------------
__global__ void gn_stats_kernel(const float* __restrict__ x) {
    int ng = blockIdx.x;  // 0..15 : n*8+g, groups are contiguous channel blocks
    const float4* base = (const float4*)(x + (size_t)ng * CPG * L_);
    float s1 = 0.f, s2 = 0.f;
    const int nv = CPG * L_ / 4;  // 32768
    for (int i = threadIdx.x; i < nv; i += 256) {
        float4 v = base[i];
        s1 += (v.x + v.y) + (v.z + v.w);
        s2 += (v.x * v.x + v.y * v.y) + (v.z * v.z + v.w * v.w);
    }
    __shared__ float r1[256], r2[256];
    r1[threadIdx.x] = s1; r2[threadIdx.x] = s2;
    __syncthreads();
    for (int s = 128; s > 0; s >>= 1) {
        if (threadIdx.x < s) {
            r1[threadIdx.x] += r1[threadIdx.x + s];
            r2[threadIdx.x] += r2[threadIdx.x + s];
        }
        __syncthreads();
    }
    if (threadIdx.x == 0) {
        float cnt  = (float)(CPG * L_);
        float mean = r1[0] / cnt;
        float var  = r2[0] / cnt - mean * mean;
        g_stats[ng * 2 + 0] = mean;
        g_stats[ng * 2 + 1] = rsqrtf(var + EPSV);
    }
}

// ---------------- GroupNorm: apply ------------------------------------------
__global__ void gn_apply_kernel(const float* __restrict__ x,
                                const float* __restrict__ w,
                                const float* __restrict__ b) {
    int i = blockIdx.x * blockDim.x + threadIdx.x;
    if (i >= NCL / 4) return;
    int e  = i * 4;
    int c  = (e / L_) & (C_ - 1);
    int ng = e / (CPG * L_);
    float mean = g_stats[ng * 2 + 0], rstd = g_stats[ng * 2 + 1];
    float sw = w[c] * rstd;
    float sb = b[c] - mean * sw;
    float4 xv = ((const float4*)x)[i];
    float4 o;
    o.x = xv.x * sw + sb; o.y = xv.y * sw + sb;
    o.z = xv.z * sw + sb; o.w = xv.w * sw + sb;
    ((float4*)g_xn)[i] = o;
}

// ---------------- QKV conv1x1 GEMM: out[d,l] = sum_c w[d,c]*xn[c,l] + b[d] --
// tile 64x64, K-step 16, 256 threads, 4x4 micro-tile per thread
__global__ void __launch_bounds__(256) gemm_qkv_kernel(
    const float* __restrict__ qw, const float* __restrict__ qb,
    const float* __restrict__ kw, const float* __restrict__ kb,
    const float* __restrict__ vw, const float* __restrict__ vb) {

    int z = blockIdx.z;            // 0..5
    int batch = z / 3, which = z - batch * 3;
    const float* w; const float* bia; float* outp;
    if      (which == 0) { w = qw; bia = qb; outp = g_q; }
    else if (which == 1) { w = kw; bia = kb; outp = g_k; }
    else                 { w = vw; bia = vb; outp = g_v; }

    const float* B   = g_xn + (size_t)batch * C_ * L_;
    float*       Out = outp + (size_t)batch * C_ * L_;
    int m0 = blockIdx.y * 64, n0 = blockIdx.x * 64;

    __shared__ __align__(16) float As[16][68];
    __shared__ __align__(16) float Bs[16][64];

    int tx = threadIdx.x & 15, ty = threadIdx.x >> 4;
    float acc[4][4];
#pragma unroll
    for (int a = 0; a < 4; a++)
#pragma unroll
        for (int c = 0; c < 4; c++) acc[a][c] = 0.f;

    for (int k0 = 0; k0 < C_; k0 += 16) {
#pragma unroll
        for (int it = 0; it < 4; ++it) {
            int idx = threadIdx.x + it * 256;
            int kk = idx & 15, mm = idx >> 4;
            As[kk][mm] = w[(m0 + mm) * C_ + k0 + kk];
        }
#pragma unroll
        for (int it = 0; it < 4; ++it) {
            int idx = threadIdx.x + it * 256;
            int nn = idx & 63, kk = idx >> 6;
            Bs[kk][nn] = B[(size_t)(k0 + kk) * L_ + n0 + nn];
        }
        __syncthreads();
#pragma unroll
        for (int kk = 0; kk < 16; kk++) {
            float4 aa = *(const float4*)&As[kk][ty * 4];
            float4 bb = *(const float4*)&Bs[kk][tx * 4];
            acc[0][0] += aa.x * bb.x; acc[0][1] += aa.x * bb.y; acc[0][2] += aa.x * bb.z; acc[0][3] += aa.x * bb.w;
            acc[1][0] += aa.y * bb.x; acc[1][1] += aa.y * bb.y; acc[1][2] += aa.y * bb.z; acc[1][3] += aa.y * bb.w;
            acc[2][0] += aa.z * bb.x; acc[2][1] += aa.z * bb.y; acc[2][2] += aa.z * bb.z; acc[2][3] += aa.z * bb.w;
            acc[3][0] += aa.w * bb.x; acc[3][1] += aa.w * bb.y; acc[3][2] += aa.w * bb.z; acc[3][3] += aa.w * bb.w;
        }
        __syncthreads();
    }
#pragma unroll
    for (int im = 0; im < 4; im++) {
        int m = m0 + ty * 4 + im;
        float bv = bia[m];
        float4 o;
        o.x = acc[im][0] + bv; o.y = acc[im][1] + bv;
        o.z = acc[im][2] + bv; o.w = acc[im][3] + bv;
        *(float4*)&Out[(size_t)m * L_ + n0 + tx * 4] = o;
    }
}

// ---------------- Flash attention: Bq=64, Bk=32, online softmax -------------
__global__ void __launch_bounds__(256) attn_kernel() {
    int l0 = blockIdx.x * 64;
    int h  = blockIdx.y;
    int n  = blockIdx.z;
    int chbase = n * C_ + h * HD;
    const float* qp = g_q + (size_t)chbase * L_;
    const float* kp = g_k + (size_t)chbase * L_;
    const float* vp = g_v + (size_t)chbase * L_;

    __shared__ __align__(16) float Qs[64 * 68];
    __shared__ __align__(16) float Ks[64 * 34];
    __shared__ __align__(16) float Vs[32 * 68];
    __shared__ __align__(16) float Ps[32 * 68];

    int t  = threadIdx.x;
    int tx = t & 15, ty = t >> 4;

    // load Q tile [c][i], c=0..63, i=0..63
#pragma unroll
    for (int it = 0; it < 16; ++it) {
        int idx = t + it * 256;
        int c = idx >> 6, i = idx & 63;
        Qs[c * 68 + i] = qp[(size_t)c * L_ + l0 + i];
    }

    float O[4][4];     // [cc][r] : c = tx*4+cc, i = ty*4+r
    float m_run[4], l_run[4];
#pragma unroll
    for (int r = 0; r < 4; r++) {
        m_run[r] = -INFINITY; l_run[r] = 0.f;
#pragma unroll
        for (int cc = 0; cc < 4; cc++) O[cc][r] = 0.f;
    }
    __syncthreads();

    const float scale = 0.125f;   // hd^-0.5, hd=64

    for (int kt = 0; kt < 128; ++kt) {
        int k0 = kt * 32;
        // load K [c][j] and V transposed [j][c]
#pragma unroll
        for (int it = 0; it < 8; ++it) {
            int idx = t + it * 256;
            int c = idx >> 5, j = idx & 31;
            float kvk = kp[(size_t)c * L_ + k0 + j];
            float kvv = vp[(size_t)c * L_ + k0 + j];
            Ks[c * 34 + j] = kvk;
            Vs[j * 68 + c] = kvv;
        }
        __syncthreads();

        // S[i][j] = sum_c Q[c][i]*K[c][j] ; thread: 4 rows x 2 cols
        float s00 = 0.f, s01 = 0.f, s10 = 0.f, s11 = 0.f;
        float s20 = 0.f, s21 = 0.f, s30 = 0.f, s31 = 0.f;
#pragma unroll 16
        for (int c = 0; c < 64; c++) {
            float4 qa = *(const float4*)&Qs[c * 68 + ty * 4];
            float2 kb = *(const float2*)&Ks[c * 34 + tx * 2];
            s00 += qa.x * kb.x; s01 += qa.x * kb.y;
            s10 += qa.y * kb.x; s11 += qa.y * kb.y;
            s20 += qa.z * kb.x; s21 += qa.z * kb.y;
            s30 += qa.w * kb.x; s31 += qa.w * kb.y;
        }
        float sv[4][2] = {{s00, s01}, {s10, s11}, {s20, s21}, {s30, s31}};

        // online softmax per query row (16 lanes with same ty hold one row)
#pragma unroll
        for (int r = 0; r < 4; r++) {
            float v0 = sv[r][0] * scale, v1 = sv[r][1] * scale;
            float mloc = fmaxf(v0, v1);
#pragma unroll
            for (int off = 8; off > 0; off >>= 1)
                mloc = fmaxf(mloc, __shfl_xor_sync(0xffffffffu, mloc, off));
            float mnew  = fmaxf(m_run[r], mloc);
            float alpha = __expf(m_run[r] - mnew);
            float p0 = __expf(v0 - mnew);
            float p1 = __expf(v1 - mnew);
            float sl = p0 + p1;
#pragma unroll
            for (int off = 8; off > 0; off >>= 1)
                sl += __shfl_xor_sync(0xffffffffu, sl, off);
            l_run[r] = l_run[r] * alpha + sl;
            m_run[r] = mnew;
#pragma unroll
            for (int cc = 0; cc < 4; cc++) O[cc][r] *= alpha;
            Ps[(tx * 2 + 0) * 68 + ty * 4 + r] = p0;
            Ps[(tx * 2 + 1) * 68 + ty * 4 + r] = p1;
        }
        __syncthreads();

        // O[c][i] += sum_j V[c][j]*P[i][j]
#pragma unroll 8
        for (int j = 0; j < 32; j++) {
            float4 va = *(const float4*)&Vs[j * 68 + tx * 4];
            float4 pa = *(const float4*)&Ps[j * 68 + ty * 4];
            O[0][0] += va.x * pa.x; O[0][1] += va.x * pa.y; O[0][2] += va.x * pa.z; O[0][3] += va.x * pa.w;
            O[1][0] += va.y * pa.x; O[1][1] += va.y * pa.y; O[1][2] += va.y * pa.z; O[1][3] += va.y * pa.w;
            O[2][0] += va.z * pa.x; O[2][1] += va.z * pa.y; O[2][2] += va.z * pa.z; O[2][3] += va.z * pa.w;
            O[3][0] += va.w * pa.x; O[3][1] += va.w * pa.y; O[3][2] += va.w * pa.z; O[3][3] += va.w * pa.w;
        }
        __syncthreads();
    }

    // normalize and store
    float* ao = g_ao + (size_t)chbase * L_;
#pragma unroll
    for (int r = 0; r < 4; r++) {
        float inv = 1.f / l_run[r];
#pragma unroll
        for (int cc = 0; cc < 4; cc++)
            ao[(size_t)(tx * 4 + cc) * L_ + l0 + ty * 4 + r] = O[cc][r] * inv;
    }
}

// ---------------- projection + bias + residual ------------------------------
__global__ void __launch_bounds__(256) gemm_proj_kernel(
    const float* __restrict__ x,
    const float* __restrict__ pw, const float* __restrict__ pb,
    float* __restrict__ out) {

    int batch = blockIdx.z;
    const float* B  = g_ao + (size_t)batch * C_ * L_;
    const float* xb = x    + (size_t)batch * C_ * L_;
    float*       Ob = out  + (size_t)batch * C_ * L_;
    int m0 = blockIdx.y * 64, n0 = blockIdx.x * 64;

    __shared__ __align__(16) float As[16][68];
    __shared__ __align__(16) float Bs[16][64];

    int tx = threadIdx.x & 15, ty = threadIdx.x >> 4;
    float acc[4][4];
#pragma unroll
    for (int a = 0; a < 4; a++)
#pragma unroll
        for (int c = 0; c < 4; c++) acc[a][c] = 0.f;

    for (int k0 = 0; k0 < C_; k0 += 16) {
#pragma unroll
        for (int it = 0; it < 4; ++it) {
            int idx = threadIdx.x + it * 256;
            int kk = idx & 15, mm = idx >> 4;
            As[kk][mm] = pw[(m0 + mm) * C_ + k0 + kk];
        }
#pragma unroll
        for (int it = 0; it < 4; ++it) {
            int idx = threadIdx.x + it * 256;
            int nn = idx & 63, kk = idx >> 6;
            Bs[kk][nn] = B[(size_t)(k0 + kk) * L_ + n0 + nn];
        }
        __syncthreads();
#pragma unroll
        for (int kk = 0; kk < 16; kk++) {
            float4 aa = *(const float4*)&As[kk][ty * 4];
            float4 bb = *(const float4*)&Bs[kk][tx * 4];
            acc[0][0] += aa.x * bb.x; acc[0][1] += aa.x * bb.y; acc[0][2] += aa.x * bb.z; acc[0][3] += aa.x * bb.w;
            acc[1][0] += aa.y * bb.x; acc[1][1] += aa.y * bb.y; acc[1][2] += aa.y * bb.z; acc[1][3] += aa.y * bb.w;
            acc[2][0] += aa.z * bb.x; acc[2][1] += aa.z * bb.y; acc[2][2] += aa.z * bb.z; acc[2][3] += aa.z * bb.w;
            acc[3][0] += aa.w * bb.x; acc[3][1] += aa.w * bb.y; acc[3][2] += aa.w * bb.z; acc[3][3] += aa.w * bb.w;
        }
        __syncthreads();
    }
#pragma unroll
    for (int im = 0; im < 4; im++) {
        int m = m0 + ty * 4 + im;
        float bv = pb[m];
        size_t off = (size_t)m * L_ + n0 + tx * 4;
        float4 xv = *(const float4*)&xb[off];
        float4 o;
        o.x = acc[im][0] + bv + xv.x; o.y = acc[im][1] + bv + xv.y;
        o.z = acc[im][2] + bv + xv.z; o.w = acc[im][3] + bv + xv.w;
        *(float4*)&Ob[off] = o;
    }
}

// ---------------- mask pass-through (int32 -> float) ------------------------
__global__ void mask_copy_kernel(const int* __restrict__ mask,
                                 float* __restrict__ out, int nmask) {
    int i = blockIdx.x * blockDim.x + threadIdx.x;
    if (i < nmask) out[NCL + i] = (float)mask[i];
}

// ---------------- launch -----------------------------------------------------
extern "C" void kernel_launch(void* const* d_in, const int* in_sizes, int n_in,
                              void* d_out, int out_size) {
    const float* x    = (const float*)d_in[0];
    const int*   mask = (const int*)  d_in[1];
    const float* nw   = (const float*)d_in[2];
    const float* nb   = (const float*)d_in[3];
    const float* qw   = (const float*)d_in[4];
    const float* qb   = (const float*)d_in[5];
    const float* kw   = (const float*)d_in[6];
    const float* kb   = (const float*)d_in[7];
    const float* vw   = (const float*)d_in[8];
    const float* vb   = (const float*)d_in[9];
    const float* pw   = (const float*)d_in[10];
    const float* pb   = (const float*)d_in[11];
    float* out = (float*)d_out;

    gn_stats_kernel<<<N_B * G_, 256>>>(x);
    gn_apply_kernel<<<(NCL / 4 + 255) / 256, 256>>>(x, nw, nb);

    dim3 gq(L_ / 64, C_ / 64, N_B * 3);
    gemm_qkv_kernel<<<gq, 256>>>(qw, qb, kw, kb, vw, vb);

    dim3 ga(L_ / 64, HEADS, N_B);
    attn_kernel<<<ga, 256>>>();

    dim3 gp(L_ / 64, C_ / 64, N_B);
    gemm_proj_kernel<<<gp, 256>>>(x, pw, pb, out);

    if (out_size > NCL) {
        int extra = out_size - NCL;
        int nm = in_sizes[1] < extra ? in_sizes[1] : extra;
        mask_copy_kernel<<<(nm + 255) / 256, 256>>>(mask, out, nm);
    }
}